// round 15
// baseline (speedup 1.0000x reference)
#include <cuda_runtime.h>
#include <cuda_fp16.h>

#define NJ 24
#define TB 32                 // samples per block (2 mma M-tiles)
#define MT 2
#define NTHREADS 768
#define LKH 72                // fp16 row stride in halves (144 B, conflict-free ldmatrix)
#define LBUF (NJ * TB * LKH)  // halves per buffer = 55296 (110592 B)
#define SMEM_BYTES (2 * LBUF * 2)   // 221184

typedef unsigned int uint;

__device__ __forceinline__ unsigned smem_u32(const void* p) {
    unsigned r;
    asm("{ .reg .u64 t; cvta.to.shared.u64 t, %1; cvt.u32.u64 %0, t; }" : "=r"(r) : "l"(p));
    return r;
}
__device__ __forceinline__ uint packh(__half a, __half b) {
    __half2 t = __halves2half2(a, b);
    return *reinterpret_cast<uint*>(&t);
}
__device__ __forceinline__ uint packf2(float a, float b) {
    __half2 t = __floats2half2_rn(a, b);
    return *reinterpret_cast<uint*>(&t);
}

// Kinematic-tree adjacency (self + parent + children), CSR. 70 nonzeros.
__constant__ int cPTR[NJ + 1] = {0,4,7,10,13,16,19,22,25,28,33,35,37,40,43,46,48,51,54,57,60,63,66,68,70};
__constant__ int cCOL[70] = {
    0,1,2,3,  1,0,4,  2,0,5,  3,0,6,  4,1,7,  5,2,8,  6,3,9,  7,4,10,
    8,5,11,  9,6,12,13,14,  10,7,  11,8,  12,9,15,  13,9,16,  14,9,17,
    15,12,  16,13,18,  17,14,19,  18,16,20,  19,17,21,  20,18,22,
    21,19,23,  22,20,  23,21};

// Weight fragments, mma.m16n8k16 B-operand per-lane order, nt-major:
// uint4 at ((n*NT + nt)*KT + kt)*32 + lane = {hi0|hi1, hi2|hi3, lo0|lo1, lo2|lo3}.
__device__ uint4 g_wf0[NJ * 8 * 1 * 32];
__device__ uint4 g_wf1[NJ * 8 * 4 * 32];
__device__ uint4 g_wf2[NJ * 8 * 4 * 32];
__device__ uint4 g_wf3[NJ * 9 * 4 * 32];

#define T0 (NJ * 8 * 1 * 32)
#define T1 (NJ * 8 * 4 * 32)
#define T3 (NJ * 9 * 4 * 32)
#define TALL (T0 + T1 + T1 + T3)

// Single merged prep kernel: 2 launches per kernel_launch call -> ncu -s 5
// lands on gnn_fused (launch #6), restoring main-kernel observability.
__global__ void prep_all(const float* __restrict__ w0, const float* __restrict__ w1,
                         const float* __restrict__ w2, const float* __restrict__ w3) {
    int gidx = blockIdx.x * blockDim.x + threadIdx.x;
    if (gidx >= TALL) return;
    const float* W; uint4* dst; int DIN, DOUT, KT, NT; int idx = gidx;
    if (idx < T0)                { W = w0; dst = g_wf0; DIN = 13; DOUT = 64; KT = 1; NT = 8; }
    else if ((idx -= T0) < T1)   { W = w1; dst = g_wf1; DIN = 64; DOUT = 64; KT = 4; NT = 8; }
    else if ((idx -= T1) < T1)   { W = w2; dst = g_wf2; DIN = 64; DOUT = 64; KT = 4; NT = 8; }
    else                         { idx -= T1; W = w3; dst = g_wf3; DIN = 64; DOUT = 65; KT = 4; NT = 9; }

    int lane = idx & 31;
    int kt = (idx >> 5) % KT;
    int nt = (idx / (32 * KT)) % NT;
    int n  = idx / (32 * KT * NT);
    int k0 = kt * 16 + (lane & 3) * 2;
    int nc = nt * 8 + (lane >> 2);

    float w[4];
    int ks[4] = {k0, k0 + 1, k0 + 8, k0 + 9};
#pragma unroll
    for (int i = 0; i < 4; i++)
        w[i] = (ks[i] < DIN && nc < DOUT) ? W[(n * DIN + ks[i]) * DOUT + nc] : 0.0f;

    __half h[4], l[4];
#pragma unroll
    for (int i = 0; i < 4; i++) {
        h[i] = __float2half_rn(w[i]);
        l[i] = __float2half_rn(w[i] - __half2float(h[i]));
    }
    uint4 o;
    o.x = packh(h[0], h[1]);
    o.y = packh(h[2], h[3]);
    o.z = packh(l[0], l[1]);
    o.w = packh(l[2], l[3]);
    dst[idx] = o;
}

#define MMA_F16(C, A0, A1, A2, A3, B0, B1)                                      \
    asm volatile(                                                               \
        "mma.sync.aligned.m16n8k16.row.col.f32.f16.f16.f32 "                    \
        "{%0,%1,%2,%3}, {%4,%5,%6,%7}, {%8,%9}, {%0,%1,%2,%3};"                 \
        : "+f"((C)[0]), "+f"((C)[1]), "+f"((C)[2]), "+f"((C)[3])                \
        : "r"(A0), "r"(A1), "r"(A2), "r"(A3), "r"(B0), "r"(B1))

// Build A-fragments from fp16 LINprev: adjacency + bias + relu -> fp16 frags.
template <int KT>
__device__ __forceinline__ void buildA(const float* __restrict__ aw,
                                       const float* __restrict__ bias,
                                       const __half* __restrict__ LINp,
                                       uint a[KT][MT][4], int n, int lane) {
    int r = lane >> 2;
    int cq = (lane & 3) * 2;
    int deg = cPTR[n + 1] - cPTR[n];
    int mm[5]; float vv[5];
#pragma unroll
    for (int e = 0; e < 5; e++) {
        int ei = cPTR[n] + ((e < deg) ? e : 0);
        mm[e] = cCOL[ei];
        vv[e] = (e < deg) ? aw[n * NJ + mm[e]] : 0.0f;
    }
#pragma unroll
    for (int kt = 0; kt < KT; kt++) {
#pragma unroll
        for (int g = 0; g < 2; g++) {
            int c = kt * 16 + cq + g * 8;
            float2 bb = *reinterpret_cast<const float2*>(bias + c);
#pragma unroll
            for (int mt = 0; mt < MT; mt++) {
#pragma unroll
                for (int h = 0; h < 2; h++) {
                    int s = mt * 16 + r + h * 8;
                    float f0 = bb.x, f1 = bb.y;
#pragma unroll
                    for (int e = 0; e < 5; e++) {
                        if (e < deg) {
                            __half2 hv = *reinterpret_cast<const __half2*>(
                                LINp + (mm[e] * TB + s) * LKH + c);
                            float2 fv = __half22float2(hv);
                            f0 = fmaf(vv[e], fv.x, f0);
                            f1 = fmaf(vv[e], fv.y, f1);
                        }
                    }
                    a[kt][mt][h + 2 * g] = packf2(fmaxf(f0, 0.f), fmaxf(f1, 0.f));
                }
            }
        }
    }
}

// MMA + store fp16 into LINnext (own joint rows). nt outer, kt inner.
template <int KT, int NT>
__device__ __forceinline__ void mma_store(const uint4* __restrict__ wf,
                                          uint a[KT][MT][4],
                                          __half* __restrict__ LINn, int n, int lane) {
    int r = lane >> 2;
    int cq = (lane & 3) * 2;
    const uint4* wp0 = wf + (size_t)(n * NT) * KT * 32 + lane;
#pragma unroll
    for (int nt = 0; nt < NT; nt++) {
        float acc[MT][4];
#pragma unroll
        for (int mt = 0; mt < MT; mt++) {
            acc[mt][0] = 0.f; acc[mt][1] = 0.f; acc[mt][2] = 0.f; acc[mt][3] = 0.f;
        }
        const uint4* wp = wp0 + (size_t)nt * KT * 32;
#pragma unroll
        for (int kt = 0; kt < KT; kt++) {
            uint4 w = wp[kt * 32];
#pragma unroll
            for (int mt = 0; mt < MT; mt++) {
                MMA_F16(acc[mt], a[kt][mt][0], a[kt][mt][1], a[kt][mt][2], a[kt][mt][3], w.x, w.y);
                MMA_F16(acc[mt], a[kt][mt][0], a[kt][mt][1], a[kt][mt][2], a[kt][mt][3], w.z, w.w);
            }
        }
        int col = nt * 8 + cq;
#pragma unroll
        for (int mt = 0; mt < MT; mt++) {
            *reinterpret_cast<__half2*>(&LINn[(n * TB + mt * 16 + r) * LKH + col]) =
                __floats2half2_rn(acc[mt][0], acc[mt][1]);
            *reinterpret_cast<__half2*>(&LINn[(n * TB + mt * 16 + r + 8) * LKH + col]) =
                __floats2half2_rn(acc[mt][2], acc[mt][3]);
        }
    }
}

// Final adjacency + bias, fp32 out to gmem (dout = 65).
__device__ __forceinline__ void adj_fin(const float* __restrict__ aw,
                                        const float* __restrict__ bias,
                                        const __half* __restrict__ LIN,
                                        float* __restrict__ outp,
                                        int nvalid, int tid) {
    for (int t = tid; t < NJ * 65 * MT; t += NTHREADS) {
        int strip = t / (NJ * 65);
        int rr = t - strip * (NJ * 65);
        int n = rr / 65;
        int j = rr - n * 65;
        int s0 = strip * 16;
        float bb = bias[j];
        float acc[16];
#pragma unroll
        for (int s = 0; s < 16; s++) acc[s] = bb;
        int e1 = cPTR[n + 1];
        for (int e = cPTR[n]; e < e1; e++) {
            int mj = cCOL[e];
            float v = aw[n * NJ + mj];
#pragma unroll
            for (int s = 0; s < 16; s++) {
                float h = __half2float(LIN[(mj * TB + s0 + s) * LKH + j]);
                acc[s] = fmaf(v, h, acc[s]);
            }
        }
#pragma unroll
        for (int s = 0; s < 16; s++)
            if (s0 + s < nvalid)
                outp[(size_t)(s0 + s) * (NJ * 65) + n * 65 + j] = acc[s];
    }
}

__global__ __launch_bounds__(NTHREADS, 1)
void gnn_fused(const float* __restrict__ x,
               const float* __restrict__ aw0, const float* __restrict__ aw1,
               const float* __restrict__ aw2, const float* __restrict__ aw3,
               const float* __restrict__ b0, const float* __restrict__ b1,
               const float* __restrict__ b2, const float* __restrict__ b3,
               float* __restrict__ out, int Btot) {
    extern __shared__ __half smh[];
    __half* LA = smh;            // ping
    __half* LB = smh + LBUF;     // pong
    int tid = threadIdx.x;
    int lane = tid & 31;
    int n = tid >> 5;            // warp = joint
    int B0 = blockIdx.x * TB;
    int nvalid = Btot - B0;
    if (nvalid > TB) nvalid = TB;

    // Stage x -> LA fp16 (root joint masked, cols 13..15 zero for the K=16 tile).
    for (int i = tid; i < TB * NJ * 16; i += NTHREADS) {
        int s = i / (NJ * 16);
        int rr = i - s * (NJ * 16);
        int nn = rr >> 4;
        int c = rr & 15;
        float v = 0.0f;
        if (s < nvalid && nn != 0 && c < 13)
            v = x[((size_t)(B0 + s) * NJ + nn) * 13 + c];
        LA[(nn * TB + s) * LKH + c] = __float2half_rn(v);
    }
    __syncthreads();

    // L0: ldmatrix own-joint x from LA, mma -> LB. (ping-pong: no write hazard)
    {
        uint a0[1][MT][4];
        int rowm = lane & 15;
        int kofs = (lane >> 4) << 3;
#pragma unroll
        for (int mt = 0; mt < MT; mt++) {
            unsigned ad = smem_u32(LA + (n * TB + mt * 16 + rowm) * LKH + kofs);
            asm volatile("ldmatrix.sync.aligned.m8n8.x4.shared.b16 {%0,%1,%2,%3}, [%4];"
                         : "=r"(a0[0][mt][0]), "=r"(a0[0][mt][1]),
                           "=r"(a0[0][mt][2]), "=r"(a0[0][mt][3]) : "r"(ad));
        }
        mma_store<1, 8>(g_wf0, a0, LB, n, lane);
    }
    __syncthreads();

    // L1..L3: fused buildA+mma per warp, ping-pong, ONE sync per layer.
    {
        uint a[4][MT][4];
        buildA<4>(aw0, b0, LB, a, n, lane);      // reads LB (neighbors)
        mma_store<4, 8>(g_wf1, a, LA, n, lane);  // writes LA (own rows)
        __syncthreads();
        buildA<4>(aw1, b1, LA, a, n, lane);
        mma_store<4, 8>(g_wf2, a, LB, n, lane);
        __syncthreads();
        buildA<4>(aw2, b2, LB, a, n, lane);
        mma_store<4, 9>(g_wf3, a, LA, n, lane);
        __syncthreads();
    }

    adj_fin(aw3, b3, LA, out + (size_t)B0 * (NJ * 65), nvalid, tid);
}

extern "C" void kernel_launch(void* const* d_in, const int* in_sizes, int n_in,
                              void* d_out, int out_size) {
    // Identify inputs by element count (robust to metadata ordering).
    const float* x = nullptr;
    const float* w[4] = {nullptr, nullptr, nullptr, nullptr};
    const float* aw[4] = {nullptr, nullptr, nullptr, nullptr};
    const float* b[4] = {nullptr, nullptr, nullptr, nullptr};
    int iw12 = 1, iaw = 0, ib = 0;
    int Btot = 0;
    for (int i = 0; i < n_in; i++) {
        int sz = in_sizes[i];
        const float* p = (const float*)d_in[i];
        if (sz == 24 * 13 * 64) {
            w[0] = p;
        } else if (sz == 24 * 64 * 64) {
            if (iw12 < 3) w[iw12++] = p;
        } else if (sz == 24 * 64 * 65) {
            w[3] = p;
        } else if (sz == 24 * 24) {
            if (iaw < 4) aw[iaw++] = p;
        } else if (sz == 64) {
            if (ib < 3) b[ib++] = p;
        } else if (sz == 65) {
            b[3] = p;
        } else {
            x = p;
            Btot = sz / (NJ * 13);
        }
    }

    (void)cudaFuncSetAttribute(gnn_fused, cudaFuncAttributeMaxDynamicSharedMemorySize, SMEM_BYTES);

    prep_all<<<(TALL + 255) / 256, 256>>>(w[0], w[1], w[2], w[3]);

    int blocks = (Btot + TB - 1) / TB;
    gnn_fused<<<blocks, NTHREADS, SMEM_BYTES>>>(
        x,
        aw[0], aw[1], aw[2], aw[3],
        b[0], b[1], b[2], b[3],
        (float*)d_out, Btot);
}